// round 1
// baseline (speedup 1.0000x reference)
#include <cuda_runtime.h>
#include <cstdint>

#define N_NODES 100000
#define N_EDGES 2000000
#define DIM     64
#define F_IN    128
#define R_REL   64
#define ER_REL  2048
#define RF_REL  64
#define NCLS    16

// ---------------- scratch (static device memory; no allocations) ----------------
__device__ __align__(16) float g_x0[N_NODES * DIM];     // projected features / reused as x2
__device__ __align__(16) float g_x1[N_NODES * DIM];     // after conv1
__device__ __align__(16) float g_agg[N_NODES * DIM];    // scatter accumulator
__device__ float g_inv[N_NODES];                        // 1/max(deg,1)
__device__ int   g_deg[N_NODES];
__device__ __align__(16) float g_wrel[R_REL * DIM];     // per-relation edge weight table

// ---------------- helpers ----------------
__device__ __forceinline__ void red_add_v4(float* addr, float4 v) {
    asm volatile("red.global.add.v4.f32 [%0], {%1, %2, %3, %4};"
                 :: "l"(addr), "f"(v.x), "f"(v.y), "f"(v.z), "f"(v.w)
                 : "memory");
}

// ---------------- kernels ----------------
__global__ void zero_kernel() {
    int i = blockIdx.x * blockDim.x + threadIdx.x;
    if (i < N_NODES * DIM) g_agg[i] = 0.f;
    if (i < N_NODES)       g_deg[i] = 0;
}

__global__ void deg_kernel(const int* __restrict__ dst) {
    int e = blockIdx.x * blockDim.x + threadIdx.x;
    if (e < N_EDGES) atomicAdd(&g_deg[dst[e]], 1);
}

__global__ void inv_kernel() {
    int n = blockIdx.x * blockDim.x + threadIdx.x;
    if (n < N_NODES) {
        int d = g_deg[n];
        g_inv[n] = 1.0f / (float)(d > 0 ? d : 1);
    }
}

// Relation graph conv (x2) + w_rel = relu-chain(rel_x) @ W_nn + b_nn.
// Tiny: single block, 256 threads, everything in SMEM.
__global__ void rel_kernel(const float* __restrict__ rel_x,
                           const int*   __restrict__ rel_ei,
                           const float* __restrict__ rel_ea,
                           const float* __restrict__ W_nn,
                           const float* __restrict__ b_nn) {
    __shared__ float h[R_REL * RF_REL];
    __shared__ float s[R_REL * RF_REL];
    __shared__ float cnt[R_REL];
    int tid = threadIdx.x;

    for (int i = tid; i < R_REL * RF_REL; i += 256) h[i] = rel_x[i];
    const int* srcr = rel_ei;
    const int* dstr = rel_ei + ER_REL;

    int warp = tid >> 5, lane = tid & 31;
    for (int it = 0; it < 2; ++it) {
        for (int i = tid; i < R_REL * RF_REL; i += 256) s[i] = 0.f;
        if (tid < R_REL) cnt[tid] = 0.f;
        __syncthreads();
        for (int e = warp; e < ER_REL; e += 8) {
            int sr = srcr[e], dr = dstr[e];
            float a = rel_ea[e];
            atomicAdd(&s[dr * RF_REL + lane],      h[sr * RF_REL + lane]      * a);
            atomicAdd(&s[dr * RF_REL + lane + 32], h[sr * RF_REL + lane + 32] * a);
            if (lane == 0) atomicAdd(&cnt[dr], 1.0f);
        }
        __syncthreads();
        for (int i = tid; i < R_REL * RF_REL; i += 256) {
            int r = i >> 6;
            float v = h[i] + s[i] / fmaxf(cnt[r], 1.0f);
            h[i] = fmaxf(v, 0.f);
        }
        __syncthreads();
    }
    // w_rel[r][d] = sum_k h[r][k] * W_nn[k][d] + b_nn[d]
    for (int i = tid; i < R_REL * DIM; i += 256) {
        int r = i >> 6, d = i & 63;
        float acc = b_nn[d];
        #pragma unroll 8
        for (int k = 0; k < RF_REL; ++k)
            acc += h[r * RF_REL + k] * W_nn[k * DIM + d];
        g_wrel[i] = acc;
    }
}

// x0 = x_in @ fc1   [100000,128]x[128,64]; 64-node tiles, 4x4 register tile/thread
__global__ void proj_kernel(const float* __restrict__ x_in,
                            const float* __restrict__ fc1) {
    __shared__ __align__(16) float fs[F_IN * DIM];   // 32 KB
    __shared__ __align__(16) float is[64 * 64];      // 16 KB
    int tid = threadIdx.x;
    for (int i = tid; i < F_IN * DIM; i += 256) fs[i] = fc1[i];

    int c4 = (tid & 15) * 4;
    int n4 = (tid >> 4) * 4;
    int ntiles = (N_NODES + 63) / 64;

    for (int t = blockIdx.x; t < ntiles; t += gridDim.x) {
        int base = t * 64;
        float acc[4][4];
        #pragma unroll
        for (int j = 0; j < 4; ++j)
            #pragma unroll
            for (int i = 0; i < 4; ++i) acc[j][i] = 0.f;

        #pragma unroll
        for (int kb = 0; kb < F_IN; kb += 64) {
            __syncthreads();
            for (int i = tid; i < 64 * 64; i += 256) {
                int n = base + (i >> 6);
                is[i] = (n < N_NODES) ? x_in[(size_t)n * F_IN + kb + (i & 63)] : 0.f;
            }
            __syncthreads();
            #pragma unroll 4
            for (int kk = 0; kk < 64; ++kk) {
                float4 f = *(const float4*)&fs[(kb + kk) * DIM + c4];
                #pragma unroll
                for (int j = 0; j < 4; ++j) {
                    float iv = is[(n4 + j) * 64 + kk];
                    acc[j][0] += iv * f.x;
                    acc[j][1] += iv * f.y;
                    acc[j][2] += iv * f.z;
                    acc[j][3] += iv * f.w;
                }
            }
        }
        #pragma unroll
        for (int j = 0; j < 4; ++j) {
            int n = base + n4 + j;
            if (n < N_NODES)
                *(float4*)&g_x0[(size_t)n * DIM + c4] =
                    make_float4(acc[j][0], acc[j][1], acc[j][2], acc[j][3]);
        }
    }
}

// Edge sweep: agg[dst] += x[src] * w_rel[etype].  16 threads per edge (float4 each).
__global__ void edge_kernel(const int* __restrict__ ei,
                            const int* __restrict__ et,
                            int which_x) {
    __shared__ __align__(16) float ws[R_REL * DIM];  // 16 KB
    for (int i = threadIdx.x; i < R_REL * DIM; i += blockDim.x) ws[i] = g_wrel[i];
    __syncthreads();

    const float* __restrict__ x = which_x ? g_x1 : g_x0;
    const int* __restrict__ src = ei;
    const int* __restrict__ dst = ei + N_EDGES;

    int gstride = (gridDim.x * blockDim.x) >> 4;
    int g    = (blockIdx.x * blockDim.x + threadIdx.x) >> 4;
    int lane = threadIdx.x & 15;

    for (int e = g; e < N_EDGES; e += gstride) {
        int s = __ldg(src + e);
        int d = __ldg(dst + e);
        int r = __ldg(et + e);
        float4 xv = *(const float4*)(x  + (size_t)s * DIM + lane * 4);
        float4 wv = *(const float4*)(ws + r * DIM + lane * 4);
        float4 m = make_float4(xv.x * wv.x, xv.y * wv.y, xv.z * wv.z, xv.w * wv.w);
        red_add_v4((float*)(g_agg + (size_t)d * DIM + lane * 4), m);
    }
}

// x_out = tanh(agg * inv + b); optionally re-zero agg for the next sweep.
__global__ void finish_kernel(const float* __restrict__ b, int which_out, int zero_agg) {
    int i = blockIdx.x * blockDim.x + threadIdx.x;
    if (i >= N_NODES * DIM) return;
    float* xo = which_out ? g_x1 : g_x0;  // which_out=1 -> x1 (after conv1), 0 -> x2 into g_x0
    int n = i >> 6, c = i & 63;
    float v = tanhf(g_agg[i] * g_inv[n] + b[c]);
    xo[i] = v;
    if (zero_agg) g_agg[i] = 0.f;
}

// out = x2 @ fc2_w + fc2_b   (x2 lives in g_x0).  16 nodes per block.
__global__ void out_kernel(const float* __restrict__ fc2w,
                           const float* __restrict__ fc2b,
                           float* __restrict__ out) {
    __shared__ float ws[DIM * NCLS];  // 4 KB
    __shared__ float xs[16 * DIM];    // 4 KB
    int tid = threadIdx.x;
    for (int i = tid; i < DIM * NCLS; i += 256) ws[i] = fc2w[i];
    int base = blockIdx.x * 16;
    for (int i = tid; i < 16 * DIM; i += 256) xs[i] = g_x0[(size_t)base * DIM + i];
    __syncthreads();
    int nl = tid >> 4, k = tid & 15;
    float acc = fc2b[k];
    #pragma unroll
    for (int c = 0; c < DIM; ++c)
        acc += xs[nl * DIM + c] * ws[c * NCLS + k];
    out[(size_t)(base + nl) * NCLS + k] = acc;
}

// ---------------- launch ----------------
extern "C" void kernel_launch(void* const* d_in, const int* in_sizes, int n_in,
                              void* d_out, int out_size) {
    const float* x_in   = (const float*)d_in[0];
    const float* rel_x  = (const float*)d_in[1];
    const int*   ei     = (const int*)  d_in[2];
    const int*   et     = (const int*)  d_in[3];
    const int*   rel_ei = (const int*)  d_in[4];
    const float* rel_ea = (const float*)d_in[5];
    const float* fc1    = (const float*)d_in[6];
    const float* W_nn   = (const float*)d_in[7];
    const float* b_nn   = (const float*)d_in[8];
    const float* b1     = (const float*)d_in[9];
    const float* b2     = (const float*)d_in[10];
    const float* fc2w   = (const float*)d_in[11];
    const float* fc2b   = (const float*)d_in[12];
    float* out = (float*)d_out;

    zero_kernel<<<(N_NODES * DIM + 255) / 256, 256>>>();
    deg_kernel<<<(N_EDGES + 255) / 256, 256>>>(ei + N_EDGES);
    inv_kernel<<<(N_NODES + 255) / 256, 256>>>();
    rel_kernel<<<1, 256>>>(rel_x, rel_ei, rel_ea, W_nn, b_nn);
    proj_kernel<<<1184, 256>>>(x_in, fc1);

    // conv1: msg = x0[src] * w_rel[etype]; mean -> x1 = tanh(. + b1); agg re-zeroed
    edge_kernel<<<2048, 256>>>(ei, et, /*which_x=*/0);
    finish_kernel<<<(N_NODES * DIM + 255) / 256, 256>>>(b1, /*which_out=*/1, /*zero_agg=*/1);

    // conv2: msg = x1[src] * w_rel[etype]; mean -> x2 = tanh(. + b2) into g_x0
    edge_kernel<<<2048, 256>>>(ei, et, /*which_x=*/1);
    finish_kernel<<<(N_NODES * DIM + 255) / 256, 256>>>(b2, /*which_out=*/0, /*zero_agg=*/0);

    out_kernel<<<N_NODES / 16, 256>>>(fc2w, fc2b, out);
}

// round 2
// speedup vs baseline: 1.5028x; 1.5028x over previous
#include <cuda_runtime.h>
#include <cstdint>

#define N_NODES 100000
#define N_EDGES 2000000
#define DIM     64
#define F_IN    128
#define R_REL   64
#define ER_REL  2048
#define RF_REL  64
#define NCLS    16

// ---------------- scratch (static device memory; no allocations) ----------------
__device__ __align__(16) float g_x0[N_NODES * DIM];     // projected features / reused as x2
__device__ __align__(16) float g_x1[N_NODES * DIM];     // after conv1
__device__ __align__(16) float g_agg[N_NODES * DIM];    // scatter accumulator
__device__ int   g_deg[N_NODES];
__device__ __align__(16) float g_wrel[R_REL * DIM];     // per-relation edge weight table

// ---------------- helpers ----------------
__device__ __forceinline__ void red_add_v4(float* addr, float4 v) {
    asm volatile("red.global.add.v4.f32 [%0], {%1, %2, %3, %4};"
                 :: "l"(addr), "f"(v.x), "f"(v.y), "f"(v.z), "f"(v.w)
                 : "memory");
}
__device__ __forceinline__ void red_add_s32(int* addr, int v) {
    asm volatile("red.global.add.s32 [%0], %1;" :: "l"(addr), "r"(v) : "memory");
}

// ---------------- kernels ----------------
__global__ void zero_kernel() {
    int i = blockIdx.x * blockDim.x + threadIdx.x;
    if (i < N_NODES * DIM / 4) ((float4*)g_agg)[i] = make_float4(0.f, 0.f, 0.f, 0.f);
    if (i < N_NODES) g_deg[i] = 0;
}

// Relation graph conv (x2) + w_rel = relu-chain(rel_x) @ W_nn + b_nn.
// Linear-algebra form: aggregation matrix A[dst][src] = sum of edge attrs,
// so each conv iteration is a 64x64x64 SMEM GEMM. One block, 1024 threads.
__global__ void rel_kernel(const float* __restrict__ rel_x,
                           const int*   __restrict__ rel_ei,
                           const float* __restrict__ rel_ea,
                           const float* __restrict__ W_nn,
                           const float* __restrict__ b_nn) {
    __shared__ __align__(16) float h[R_REL * RF_REL];   // 16 KB
    __shared__ __align__(16) float A[R_REL * R_REL];    // 16 KB (reused for W_nn)
    __shared__ float cnt[R_REL];
    int tid = threadIdx.x;  // 1024

    for (int i = tid; i < R_REL * RF_REL; i += 1024) { h[i] = rel_x[i]; A[i] = 0.f; }
    if (tid < R_REL) cnt[tid] = 0.f;
    __syncthreads();

    for (int e = tid; e < ER_REL; e += 1024) {
        int sr = rel_ei[e];
        int dr = rel_ei[ER_REL + e];
        float a = rel_ea[e];
        atomicAdd(&A[dr * R_REL + sr], a);
        atomicAdd(&cnt[dr], 1.0f);
    }
    __syncthreads();

    int r  = tid >> 4;          // 64 rows, 16 threads per row
    int c4 = (tid & 15) * 4;    // 4 consecutive cols per thread
    float inv = 1.0f / fmaxf(cnt[r], 1.0f);

    #pragma unroll
    for (int it = 0; it < 2; ++it) {
        float4 acc = make_float4(0.f, 0.f, 0.f, 0.f);
        #pragma unroll 8
        for (int k = 0; k < R_REL; ++k) {
            float a = A[r * R_REL + k];
            float4 hv = *(const float4*)&h[k * RF_REL + c4];
            acc.x += a * hv.x; acc.y += a * hv.y;
            acc.z += a * hv.z; acc.w += a * hv.w;
        }
        __syncthreads();  // all reads of h done
        float4 hv = *(const float4*)&h[r * RF_REL + c4];
        hv.x = fmaxf(hv.x + acc.x * inv, 0.f);
        hv.y = fmaxf(hv.y + acc.y * inv, 0.f);
        hv.z = fmaxf(hv.z + acc.z * inv, 0.f);
        hv.w = fmaxf(hv.w + acc.w * inv, 0.f);
        *(float4*)&h[r * RF_REL + c4] = hv;
        __syncthreads();
    }

    // Reuse A's smem for W_nn, then w_rel = h @ W_nn + b_nn
    for (int i = tid; i < RF_REL * DIM; i += 1024) A[i] = W_nn[i];
    __syncthreads();
    float4 acc = make_float4(b_nn[c4], b_nn[c4 + 1], b_nn[c4 + 2], b_nn[c4 + 3]);
    #pragma unroll 8
    for (int k = 0; k < RF_REL; ++k) {
        float hv = h[r * RF_REL + k];
        float4 wv = *(const float4*)&A[k * DIM + c4];
        acc.x += hv * wv.x; acc.y += hv * wv.y;
        acc.z += hv * wv.z; acc.w += hv * wv.w;
    }
    *(float4*)&g_wrel[r * DIM + c4] = acc;
}

// x0 = x_in @ fc1   [100000,128]x[128,64]; 64-node tiles, 4x4 register tile/thread
__global__ void proj_kernel(const float* __restrict__ x_in,
                            const float* __restrict__ fc1) {
    __shared__ __align__(16) float fs[F_IN * DIM];   // 32 KB
    __shared__ __align__(16) float is[64 * 64];      // 16 KB
    int tid = threadIdx.x;
    for (int i = tid; i < F_IN * DIM; i += 256) fs[i] = fc1[i];

    int c4 = (tid & 15) * 4;
    int n4 = (tid >> 4) * 4;
    int ntiles = (N_NODES + 63) / 64;

    for (int t = blockIdx.x; t < ntiles; t += gridDim.x) {
        int base = t * 64;
        float acc[4][4];
        #pragma unroll
        for (int j = 0; j < 4; ++j)
            #pragma unroll
            for (int i = 0; i < 4; ++i) acc[j][i] = 0.f;

        #pragma unroll
        for (int kb = 0; kb < F_IN; kb += 64) {
            __syncthreads();
            for (int i = tid; i < 64 * 64; i += 256) {
                int n = base + (i >> 6);
                is[i] = (n < N_NODES) ? x_in[(size_t)n * F_IN + kb + (i & 63)] : 0.f;
            }
            __syncthreads();
            #pragma unroll 4
            for (int kk = 0; kk < 64; ++kk) {
                float4 f = *(const float4*)&fs[(kb + kk) * DIM + c4];
                #pragma unroll
                for (int j = 0; j < 4; ++j) {
                    float iv = is[(n4 + j) * 64 + kk];
                    acc[j][0] += iv * f.x;
                    acc[j][1] += iv * f.y;
                    acc[j][2] += iv * f.z;
                    acc[j][3] += iv * f.w;
                }
            }
        }
        #pragma unroll
        for (int j = 0; j < 4; ++j) {
            int n = base + n4 + j;
            if (n < N_NODES)
                *(float4*)&g_x0[(size_t)n * DIM + c4] =
                    make_float4(acc[j][0], acc[j][1], acc[j][2], acc[j][3]);
        }
    }
}

// Edge sweep: agg[dst] += x[src] * w_rel[etype].  16 threads per edge (float4 each).
// count_deg!=0: lane 0 also bumps g_deg[dst].
__global__ void edge_kernel(const int* __restrict__ ei,
                            const int* __restrict__ et,
                            int which_x, int count_deg) {
    __shared__ __align__(16) float ws[R_REL * DIM];  // 16 KB
    for (int i = threadIdx.x; i < R_REL * DIM; i += blockDim.x) ws[i] = g_wrel[i];
    __syncthreads();

    const float* __restrict__ x = which_x ? g_x1 : g_x0;
    const int* __restrict__ src = ei;
    const int* __restrict__ dst = ei + N_EDGES;

    int gstride = (gridDim.x * blockDim.x) >> 4;
    int g    = (blockIdx.x * blockDim.x + threadIdx.x) >> 4;
    int lane = threadIdx.x & 15;

    for (int e = g; e < N_EDGES; e += gstride) {
        int s = __ldg(src + e);
        int d = __ldg(dst + e);
        int r = __ldg(et + e);
        float4 xv = *(const float4*)(x  + (size_t)s * DIM + lane * 4);
        float4 wv = *(const float4*)(ws + r * DIM + lane * 4);
        float4 m = make_float4(xv.x * wv.x, xv.y * wv.y, xv.z * wv.z, xv.w * wv.w);
        red_add_v4((float*)(g_agg + (size_t)d * DIM + lane * 4), m);
        if (count_deg && lane == 0) red_add_s32(&g_deg[d], 1);
    }
}

// x_out = tanh(agg / max(deg,1) + b); optionally re-zero agg for the next sweep.
__global__ void finish_kernel(const float* __restrict__ b, int which_out, int zero_agg) {
    int i = blockIdx.x * blockDim.x + threadIdx.x;
    if (i >= N_NODES * DIM) return;
    float* xo = which_out ? g_x1 : g_x0;  // 1 -> x1 (after conv1), 0 -> x2 into g_x0
    int n = i >> 6, c = i & 63;
    int d = g_deg[n];
    float inv = 1.0f / (float)(d > 0 ? d : 1);
    float v = tanhf(g_agg[i] * inv + b[c]);
    xo[i] = v;
    if (zero_agg) g_agg[i] = 0.f;
}

// out = x2 @ fc2_w + fc2_b   (x2 lives in g_x0).  16 nodes per block.
__global__ void out_kernel(const float* __restrict__ fc2w,
                           const float* __restrict__ fc2b,
                           float* __restrict__ out) {
    __shared__ float ws[DIM * NCLS];  // 4 KB
    __shared__ float xs[16 * DIM];    // 4 KB
    int tid = threadIdx.x;
    for (int i = tid; i < DIM * NCLS; i += 256) ws[i] = fc2w[i];
    int base = blockIdx.x * 16;
    for (int i = tid; i < 16 * DIM; i += 256) xs[i] = g_x0[(size_t)base * DIM + i];
    __syncthreads();
    int nl = tid >> 4, k = tid & 15;
    float acc = fc2b[k];
    #pragma unroll
    for (int c = 0; c < DIM; ++c)
        acc += xs[nl * DIM + c] * ws[c * NCLS + k];
    out[(size_t)(base + nl) * NCLS + k] = acc;
}

// ---------------- launch ----------------
extern "C" void kernel_launch(void* const* d_in, const int* in_sizes, int n_in,
                              void* d_out, int out_size) {
    const float* x_in   = (const float*)d_in[0];
    const float* rel_x  = (const float*)d_in[1];
    const int*   ei     = (const int*)  d_in[2];
    const int*   et     = (const int*)  d_in[3];
    const int*   rel_ei = (const int*)  d_in[4];
    const float* rel_ea = (const float*)d_in[5];
    const float* fc1    = (const float*)d_in[6];
    const float* W_nn   = (const float*)d_in[7];
    const float* b_nn   = (const float*)d_in[8];
    const float* b1     = (const float*)d_in[9];
    const float* b2     = (const float*)d_in[10];
    const float* fc2w   = (const float*)d_in[11];
    const float* fc2b   = (const float*)d_in[12];
    float* out = (float*)d_out;

    zero_kernel<<<(N_NODES * DIM / 4 + 255) / 256, 256>>>();
    rel_kernel<<<1, 1024>>>(rel_x, rel_ei, rel_ea, W_nn, b_nn);
    proj_kernel<<<1184, 256>>>(x_in, fc1);

    // conv1: msg = x0[src] * w_rel[etype]; mean -> x1 = tanh(. + b1); agg re-zeroed
    edge_kernel<<<2048, 256>>>(ei, et, /*which_x=*/0, /*count_deg=*/1);
    finish_kernel<<<(N_NODES * DIM + 255) / 256, 256>>>(b1, /*which_out=*/1, /*zero_agg=*/1);

    // conv2: msg = x1[src] * w_rel[etype]; mean -> x2 = tanh(. + b2) into g_x0
    edge_kernel<<<2048, 256>>>(ei, et, /*which_x=*/1, /*count_deg=*/0);
    finish_kernel<<<(N_NODES * DIM + 255) / 256, 256>>>(b2, /*which_out=*/0, /*zero_agg=*/0);

    out_kernel<<<N_NODES / 16, 256>>>(fc2w, fc2b, out);
}

// round 4
// speedup vs baseline: 1.5634x; 1.0403x over previous
#include <cuda_runtime.h>
#include <cuda_fp16.h>
#include <cstdint>

#define N_NODES 100000
#define N_EDGES 2000000
#define DIM     64
#define F_IN    128
#define R_REL   64
#define ER_REL  2048
#define RF_REL  64
#define NCLS    16

// ---------------- scratch (static device memory; no allocations) ----------------
__device__ __align__(16) float g_x0[N_NODES * DIM];        // projected features / reused as x2
__device__ __align__(16) float g_x1[N_NODES * DIM];        // after conv1
__device__ __align__(16) float g_agg[N_NODES * DIM];       // scatter accumulator
__device__ __align__(16) __half2 g_x0h[N_NODES * DIM / 2]; // fp16 mirror of x0
__device__ __align__(16) __half2 g_x1h[N_NODES * DIM / 2]; // fp16 mirror of x1
__device__ int   g_deg[N_NODES];
__device__ __align__(16) float g_wrel[R_REL * DIM];        // per-relation edge weight table

// ---------------- helpers ----------------
__device__ __forceinline__ void red_add_v4(float* addr, float4 v) {
    asm volatile("red.global.add.v4.f32 [%0], {%1, %2, %3, %4};"
                 :: "l"(addr), "f"(v.x), "f"(v.y), "f"(v.z), "f"(v.w)
                 : "memory");
}
__device__ __forceinline__ void red_add_s32(int* addr, int v) {
    asm volatile("red.global.add.s32 [%0], %1;" :: "l"(addr), "r"(v) : "memory");
}

// ---------------- kernels ----------------
__global__ void zero_kernel() {
    int i = blockIdx.x * blockDim.x + threadIdx.x;
    if (i < N_NODES * DIM / 4) ((float4*)g_agg)[i] = make_float4(0.f, 0.f, 0.f, 0.f);
    if (i < N_NODES) g_deg[i] = 0;
}

// Relation graph conv (x2) + w_rel = relu-chain(rel_x) @ W_nn + b_nn.
// Linear-algebra form: aggregation matrix A[dst][src] = sum of edge attrs,
// so each conv iteration is a 64x64x64 SMEM GEMM. One block, 1024 threads.
__global__ void rel_kernel(const float* __restrict__ rel_x,
                           const int*   __restrict__ rel_ei,
                           const float* __restrict__ rel_ea,
                           const float* __restrict__ W_nn,
                           const float* __restrict__ b_nn) {
    __shared__ __align__(16) float h[R_REL * RF_REL];   // 16 KB
    __shared__ __align__(16) float A[R_REL * R_REL];    // 16 KB (reused for W_nn)
    __shared__ float cnt[R_REL];
    int tid = threadIdx.x;  // 1024

    for (int i = tid; i < R_REL * RF_REL; i += 1024) { h[i] = rel_x[i]; A[i] = 0.f; }
    if (tid < R_REL) cnt[tid] = 0.f;
    __syncthreads();

    for (int e = tid; e < ER_REL; e += 1024) {
        int sr = rel_ei[e];
        int dr = rel_ei[ER_REL + e];
        float a = rel_ea[e];
        atomicAdd(&A[dr * R_REL + sr], a);
        atomicAdd(&cnt[dr], 1.0f);
    }
    __syncthreads();

    int r  = tid >> 4;          // 64 rows, 16 threads per row
    int c4 = (tid & 15) * 4;    // 4 consecutive cols per thread
    float inv = 1.0f / fmaxf(cnt[r], 1.0f);

    #pragma unroll
    for (int it = 0; it < 2; ++it) {
        float4 acc = make_float4(0.f, 0.f, 0.f, 0.f);
        #pragma unroll 8
        for (int k = 0; k < R_REL; ++k) {
            float a = A[r * R_REL + k];
            float4 hv = *(const float4*)&h[k * RF_REL + c4];
            acc.x += a * hv.x; acc.y += a * hv.y;
            acc.z += a * hv.z; acc.w += a * hv.w;
        }
        __syncthreads();  // all reads of h done
        float4 hv = *(const float4*)&h[r * RF_REL + c4];
        hv.x = fmaxf(hv.x + acc.x * inv, 0.f);
        hv.y = fmaxf(hv.y + acc.y * inv, 0.f);
        hv.z = fmaxf(hv.z + acc.z * inv, 0.f);
        hv.w = fmaxf(hv.w + acc.w * inv, 0.f);
        *(float4*)&h[r * RF_REL + c4] = hv;
        __syncthreads();
    }

    // Reuse A's smem for W_nn, then w_rel = h @ W_nn + b_nn
    for (int i = tid; i < RF_REL * DIM; i += 1024) A[i] = W_nn[i];
    __syncthreads();
    float4 acc = make_float4(b_nn[c4], b_nn[c4 + 1], b_nn[c4 + 2], b_nn[c4 + 3]);
    #pragma unroll 8
    for (int k = 0; k < RF_REL; ++k) {
        float hv = h[r * RF_REL + k];
        float4 wv = *(const float4*)&A[k * DIM + c4];
        acc.x += hv * wv.x; acc.y += hv * wv.y;
        acc.z += hv * wv.z; acc.w += hv * wv.w;
    }
    *(float4*)&g_wrel[r * DIM + c4] = acc;
}

// x0 = x_in @ fc1   [100000,128]x[128,64]; 64-node tiles, 4x4 register tile/thread.
// Input tile is XOR-swizzled so the scalar reads are bank-conflict-free.
__global__ void proj_kernel(const float* __restrict__ x_in,
                            const float* __restrict__ fc1) {
    __shared__ __align__(16) float fs[F_IN * DIM];   // 32 KB
    __shared__ __align__(16) float is[64 * 64];      // 16 KB, swizzled
    int tid = threadIdx.x;
    for (int i = tid; i < F_IN * DIM; i += 256) fs[i] = fc1[i];

    int c4 = (tid & 15) * 4;
    int n4 = (tid >> 4) * 4;
    int sw = tid >> 4;          // == (n4+j)>>2 for j in 0..3
    int ntiles = (N_NODES + 63) / 64;

    for (int t = blockIdx.x; t < ntiles; t += gridDim.x) {
        int base = t * 64;
        float acc[4][4];
        #pragma unroll
        for (int j = 0; j < 4; ++j)
            #pragma unroll
            for (int i = 0; i < 4; ++i) acc[j][i] = 0.f;

        #pragma unroll
        for (int kb = 0; kb < F_IN; kb += 64) {
            __syncthreads();
            for (int i = tid; i < 64 * 64; i += 256) {
                int nn = i >> 6, k = i & 63;
                int n = base + nn;
                is[nn * 64 + (k ^ (nn >> 2))] =
                    (n < N_NODES) ? x_in[(size_t)n * F_IN + kb + k] : 0.f;
            }
            __syncthreads();
            #pragma unroll 4
            for (int kk = 0; kk < 64; ++kk) {
                float4 f = *(const float4*)&fs[(kb + kk) * DIM + c4];
                int ks = kk ^ sw;
                #pragma unroll
                for (int j = 0; j < 4; ++j) {
                    float iv = is[(n4 + j) * 64 + ks];
                    acc[j][0] += iv * f.x;
                    acc[j][1] += iv * f.y;
                    acc[j][2] += iv * f.z;
                    acc[j][3] += iv * f.w;
                }
            }
        }
        #pragma unroll
        for (int j = 0; j < 4; ++j) {
            int n = base + n4 + j;
            if (n < N_NODES) {
                *(float4*)&g_x0[(size_t)n * DIM + c4] =
                    make_float4(acc[j][0], acc[j][1], acc[j][2], acc[j][3]);
                __half2 h0 = __floats2half2_rn(acc[j][0], acc[j][1]);
                __half2 h1 = __floats2half2_rn(acc[j][2], acc[j][3]);
                uint2 p = make_uint2(*(uint32_t*)&h0, *(uint32_t*)&h1);
                *(uint2*)(g_x0h + (size_t)n * 32 + (c4 >> 1)) = p;
            }
        }
    }
}

// Edge sweep: agg[dst] += x[src] * w_rel[etype].  16 threads per edge.
// Gather is fp16 (128 B/row); weights fp32 from SMEM; scatter fp32 RED.v4.
// count_deg!=0: lane 0 also bumps g_deg[dst].
__global__ void edge_kernel(const int* __restrict__ ei,
                            const int* __restrict__ et,
                            int which_x, int count_deg) {
    __shared__ __align__(16) float ws[R_REL * DIM];  // 16 KB
    for (int i = threadIdx.x; i < R_REL * DIM; i += blockDim.x) ws[i] = g_wrel[i];
    __syncthreads();

    const __half2* __restrict__ xh = which_x ? g_x1h : g_x0h;
    const int* __restrict__ src = ei;
    const int* __restrict__ dst = ei + N_EDGES;

    int gstride = (gridDim.x * blockDim.x) >> 4;
    int g    = (blockIdx.x * blockDim.x + threadIdx.x) >> 4;
    int lane = threadIdx.x & 15;

    #pragma unroll 2
    for (int e = g; e < N_EDGES; e += gstride) {
        int s = __ldg(src + e);
        int d = __ldg(dst + e);
        int r = __ldg(et + e);
        uint2 p = *(const uint2*)(xh + (size_t)s * 32 + lane * 2);
        float2 f0 = __half22float2(*(__half2*)&p.x);
        float2 f1 = __half22float2(*(__half2*)&p.y);
        float4 wv = *(const float4*)(ws + r * DIM + lane * 4);
        float4 m = make_float4(f0.x * wv.x, f0.y * wv.y, f1.x * wv.z, f1.y * wv.w);
        red_add_v4((float*)(g_agg + (size_t)d * DIM + lane * 4), m);
        if (count_deg && lane == 0) red_add_s32(&g_deg[d], 1);
    }
}

// x_out = tanh(agg / max(deg,1) + b). float4 per thread.
// store_h: also write fp16 mirror. zero_agg: re-zero accumulator.
__global__ void finish_kernel(const float* __restrict__ b,
                              int which_out, int zero_agg, int store_h) {
    int i = blockIdx.x * blockDim.x + threadIdx.x;
    if (i >= N_NODES * (DIM / 4)) return;
    int n = i >> 4, c4 = (i & 15) * 4;
    float4 v = ((const float4*)g_agg)[i];
    int d = g_deg[n];
    float inv = 1.0f / (float)(d > 0 ? d : 1);
    float4 bb = *(const float4*)(b + c4);
    v.x = tanhf(v.x * inv + bb.x);
    v.y = tanhf(v.y * inv + bb.y);
    v.z = tanhf(v.z * inv + bb.z);
    v.w = tanhf(v.w * inv + bb.w);
    float* xo = which_out ? g_x1 : g_x0;
    ((float4*)xo)[i] = v;
    if (store_h) {
        __half2* xoh = which_out ? g_x1h : g_x0h;
        __half2 h0 = __floats2half2_rn(v.x, v.y);
        __half2 h1 = __floats2half2_rn(v.z, v.w);
        uint2 p = make_uint2(*(uint32_t*)&h0, *(uint32_t*)&h1);
        *(uint2*)(xoh + (size_t)n * 32 + (c4 >> 1)) = p;
    }
    if (zero_agg) ((float4*)g_agg)[i] = make_float4(0.f, 0.f, 0.f, 0.f);
}

// out = x2 @ fc2_w + fc2_b   (x2 lives in g_x0).  16 nodes per block.
__global__ void out_kernel(const float* __restrict__ fc2w,
                           const float* __restrict__ fc2b,
                           float* __restrict__ out) {
    __shared__ float ws[DIM * NCLS];  // 4 KB
    __shared__ float xs[16 * DIM];    // 4 KB
    int tid = threadIdx.x;
    for (int i = tid; i < DIM * NCLS; i += 256) ws[i] = fc2w[i];
    int base = blockIdx.x * 16;
    for (int i = tid; i < 16 * DIM; i += 256) xs[i] = g_x0[(size_t)base * DIM + i];
    __syncthreads();
    int nl = tid >> 4, k = tid & 15;
    float acc = fc2b[k];
    #pragma unroll
    for (int c = 0; c < DIM; ++c)
        acc += xs[nl * DIM + c] * ws[c * NCLS + k];
    out[(size_t)(base + nl) * NCLS + k] = acc;
}

// ---------------- launch ----------------
extern "C" void kernel_launch(void* const* d_in, const int* in_sizes, int n_in,
                              void* d_out, int out_size) {
    const float* x_in   = (const float*)d_in[0];
    const float* rel_x  = (const float*)d_in[1];
    const int*   ei     = (const int*)  d_in[2];
    const int*   et     = (const int*)  d_in[3];
    const int*   rel_ei = (const int*)  d_in[4];
    const float* rel_ea = (const float*)d_in[5];
    const float* fc1    = (const float*)d_in[6];
    const float* W_nn   = (const float*)d_in[7];
    const float* b_nn   = (const float*)d_in[8];
    const float* b1     = (const float*)d_in[9];
    const float* b2     = (const float*)d_in[10];
    const float* fc2w   = (const float*)d_in[11];
    const float* fc2b   = (const float*)d_in[12];
    float* out = (float*)d_out;

    zero_kernel<<<(N_NODES * DIM / 4 + 255) / 256, 256>>>();
    rel_kernel<<<1, 1024>>>(rel_x, rel_ei, rel_ea, W_nn, b_nn);
    proj_kernel<<<1184, 256>>>(x_in, fc1);

    // conv1: msg = x0[src] * w_rel[etype]; mean -> x1 = tanh(. + b1); agg re-zeroed
    edge_kernel<<<2048, 256>>>(ei, et, /*which_x=*/0, /*count_deg=*/1);
    finish_kernel<<<(N_NODES * 16 + 255) / 256, 256>>>(b1, 1, /*zero_agg=*/1, /*store_h=*/1);

    // conv2: msg = x1[src] * w_rel[etype]; mean -> x2 = tanh(. + b2) into g_x0
    edge_kernel<<<2048, 256>>>(ei, et, /*which_x=*/1, /*count_deg=*/0);
    finish_kernel<<<(N_NODES * 16 + 255) / 256, 256>>>(b2, 0, /*zero_agg=*/0, /*store_h=*/0);

    out_kernel<<<N_NODES / 16, 256>>>(fc2w, fc2b, out);
}